// round 14
// baseline (speedup 1.0000x reference)
#include <cuda_runtime.h>
#include <cuda_fp16.h>
#include <cstdint>
#include <cstddef>

// Problem constants
#define B_ROWS 8192
#define FEAT   7680
#define HID    512

// Scratch (allocation-free: __device__ globals)
__device__ __half g_w1h[(size_t)HID * FEAT];         // 7.9 MB
__device__ __half g_w2h[(size_t)HID * HID];          // 0.5 MB
__device__ __half g_h1[(size_t)B_ROWS * HID];        // 8.4 MB (fp16 activations)
__device__ __half g_h2[(size_t)B_ROWS * HID];        // 8.4 MB (fp16 activations)
__device__ int    g_idx64;

// ---------------------------------------------------------------------------
// helpers
// ---------------------------------------------------------------------------
__device__ __forceinline__ void cp_async16(uint32_t smem_dst, const void* gptr) {
    asm volatile("cp.async.cg.shared.global [%0], [%1], 16;"
                 :: "r"(smem_dst), "l"(gptr));
}
__device__ __forceinline__ void cp_commit() {
    asm volatile("cp.async.commit_group;");
}
__device__ __forceinline__ uint32_t packf2(float x, float y) {
    __half2 h = __floats2half2_rn(x, y);
    return *(uint32_t*)&h;
}

// ---------------------------------------------------------------------------
// fp32 -> fp16 conversion for the two weight matrices (8.4MB, ~3us).
// ---------------------------------------------------------------------------
__device__ __forceinline__ void cvt_range(const float4* __restrict__ in,
                                          uint2* __restrict__ out, int n4,
                                          int gtid, int stride)
{
    for (int i = gtid; i < n4; i += stride) {
        float4 v = in[i];
        uint2 u;
        u.x = packf2(v.x, v.y);
        u.y = packf2(v.z, v.w);
        out[i] = u;
    }
}

__global__ void convert_w_kernel(const float4* __restrict__ w1, uint2* __restrict__ w1_o,
                                 const float4* __restrict__ w2, uint2* __restrict__ w2_o)
{
    const int gtid   = blockIdx.x * blockDim.x + threadIdx.x;
    const int stride = gridDim.x * blockDim.x;
    cvt_range(w1, w1_o, (HID * FEAT) / 4, gtid, stride);
    cvt_range(w2, w2_o, (HID * HID) / 4,  gtid, stride);
}

// ---------------------------------------------------------------------------
// scene_idx dtype detection (int32 vs int64).
// ---------------------------------------------------------------------------
__global__ void detect_idx_kernel(const int* __restrict__ p) {
    int is64 = 1;
    for (int i = 0; i < 64; i++) {
        if (p[2 * i + 1] != 0) { is64 = 0; break; }
    }
    g_idx64 = is64;
}

// ---------------------------------------------------------------------------
// Pipelined FP16 GEMM (f32 accumulate):
//   C[M,N] = act( A[M,K] @ B[N,K]^T + bias[N] )
// CTA tile 128x256x64, 8 warps 2(M) x 4(N), warp tile 64x64 via m16n8k16
// (proven R10 loop, measured at the legacy-HMMA roofline).
// AF32 mode: A stays fp32 in GMEM; cp.async stages it as fp32 in SMEM (no
// register-file round trip -- R12's failure mode), and the A fragment path
// does float2 LDS + cvt-pack to fp16x2 (+64 CVT/warp/kt, ~256 cyc/SMSP vs
// ~4000 budget). This deletes the standalone 378MB feat convert pass.
// 3-stage cp.async pipeline, single __syncthreads per kt, occupancy 1.
// ---------------------------------------------------------------------------
template<int BM, int BN, int BK, int STAGES, bool RELU, bool AF32, typename OutT>
__global__ void __launch_bounds__(256, 1) gemm_relu_f16(
    const void* __restrict__ Av, const __half* __restrict__ Bw,
    const float* __restrict__ bias, OutT* __restrict__ C,
    int M, int N, int K)
{
    constexpr int SKA32 = BK + 4;               // floats per fp32 A row (68)
    constexpr int SKA16 = BK + 8;               // halves per fp16 A row (72)
    constexpr int SKB   = BK + 8;               // halves per B row
    constexpr int A_H   = AF32 ? BM * SKA32 * 2 : BM * SKA16;  // in halves
    constexpr int STAGE_H = A_H + BN * SKB;

    extern __shared__ __half smem[];

    const int tid  = threadIdx.x;
    const int warp = tid >> 5;
    const int lane = tid & 31;
    const int g    = lane >> 2;   // group id (0..7)
    const int t4   = lane & 3;    // thread in group (0..3)

    const int m0 = blockIdx.y * BM;
    const int n0 = blockIdx.x * BN;

    const int wm = (warp & 1) * 64;   // warp M offset
    const int wn = (warp >> 1) * 64;  // warp N offset

    float acc[4][8][4];
    #pragma unroll
    for (int i = 0; i < 4; i++)
        #pragma unroll
        for (int j = 0; j < 8; j++)
            #pragma unroll
            for (int k = 0; k < 4; k++) acc[i][j][k] = 0.f;

    auto load_stage = [&](int s, int k0) {
        if (AF32) {
            const float* Af = (const float*)Av;
            float* As = (float*)(smem + s * STAGE_H);
            // 128 rows x 16 chunks (16B) = 2048 / 256 threads = 8 each
            #pragma unroll
            for (int i = 0; i < (BM * 16) / 256; i++) {
                int q = tid + i * 256;
                int row = q >> 4, c = q & 15;
                cp_async16((uint32_t)__cvta_generic_to_shared(As + row * SKA32 + c * 4),
                           Af + (size_t)(m0 + row) * K + k0 + c * 4);
            }
        } else {
            const __half* A = (const __half*)Av;
            __half* As = smem + s * STAGE_H;
            #pragma unroll
            for (int i = 0; i < (BM * 8) / 256; i++) {
                int q = tid + i * 256;
                int row = q >> 3, c = q & 7;
                cp_async16((uint32_t)__cvta_generic_to_shared(As + row * SKA16 + c * 8),
                           A + (size_t)(m0 + row) * K + k0 + c * 8);
            }
        }
        __half* Bs = smem + s * STAGE_H + A_H;
        #pragma unroll
        for (int i = 0; i < (BN * 8) / 256; i++) {
            int q = tid + i * 256;
            int row = q >> 3, c = q & 7;
            cp_async16((uint32_t)__cvta_generic_to_shared(Bs + row * SKB + c * 8),
                       Bw + (size_t)(n0 + row) * K + k0 + c * 8);
        }
    };

    const int KT = K / BK;

    #pragma unroll
    for (int s = 0; s < STAGES - 1; s++) {
        load_stage(s, s * BK);
        cp_commit();
    }

    int buf = 0;
    for (int kt = 0; kt < KT; kt++) {
        asm volatile("cp.async.wait_group %0;" :: "n"(STAGES - 2));
        __syncthreads();

        // Next stage targets slot (kt-1)%STAGES, fully consumed last iter;
        // the barrier above orders it.
        int kn = kt + STAGES - 1;
        if (kn < KT) load_stage(kn % STAGES, kn * BK);
        cp_commit();

        const __half* Bs = smem + buf * STAGE_H + A_H;

        #pragma unroll
        for (int kk = 0; kk < BK / 16; kk++) {
            uint32_t b[8][2];
            #pragma unroll
            for (int ni = 0; ni < 8; ni++) {
                const __half* bp = Bs + (wn + ni * 8 + g) * SKB + kk * 16 + t4 * 2;
                b[ni][0] = *(const uint32_t*)bp;
                b[ni][1] = *(const uint32_t*)(bp + 8);
            }
            #pragma unroll
            for (int mi = 0; mi < 4; mi++) {
                uint32_t a0, a1, a2, a3;
                if (AF32) {
                    const float* Af32 = (const float*)(smem + buf * STAGE_H);
                    const float* ap   = Af32 + (wm + mi * 16 + g) * SKA32 + kk * 16 + t4 * 2;
                    const float* ap8  = ap + 8 * SKA32;
                    float2 v0 = *(const float2*)ap;
                    float2 v1 = *(const float2*)ap8;
                    float2 v2 = *(const float2*)(ap + 8);
                    float2 v3 = *(const float2*)(ap8 + 8);
                    a0 = packf2(v0.x, v0.y);
                    a1 = packf2(v1.x, v1.y);
                    a2 = packf2(v2.x, v2.y);
                    a3 = packf2(v3.x, v3.y);
                } else {
                    const __half* As16 = smem + buf * STAGE_H;
                    const __half* ap   = As16 + (wm + mi * 16 + g) * SKA16 + kk * 16 + t4 * 2;
                    const __half* ap8  = ap + 8 * SKA16;
                    a0 = *(const uint32_t*)ap;
                    a1 = *(const uint32_t*)ap8;
                    a2 = *(const uint32_t*)(ap + 8);
                    a3 = *(const uint32_t*)(ap8 + 8);
                }
                #pragma unroll
                for (int ni = 0; ni < 8; ni++) {
                    float* d = acc[mi][ni];
                    asm volatile(
                        "mma.sync.aligned.m16n8k16.row.col.f32.f16.f16.f32 "
                        "{%0,%1,%2,%3}, {%4,%5,%6,%7}, {%8,%9}, {%0,%1,%2,%3};"
                        : "+f"(d[0]), "+f"(d[1]), "+f"(d[2]), "+f"(d[3])
                        : "r"(a0), "r"(a1), "r"(a2), "r"(a3),
                          "r"(b[ni][0]), "r"(b[ni][1]));
                }
            }
        }

        buf++;
        if (buf == STAGES) buf = 0;
    }

    // Epilogue: bias + optional ReLU; cols (2t4, 2t4+1) contiguous.
    #pragma unroll
    for (int mi = 0; mi < 4; mi++) {
        int row0 = m0 + wm + mi * 16 + g;
        #pragma unroll
        for (int ni = 0; ni < 8; ni++) {
            int col = n0 + wn + ni * 8 + t4 * 2;
            float bb0 = bias[col], bb1 = bias[col + 1];
            float v0 = acc[mi][ni][0] + bb0;
            float v1 = acc[mi][ni][1] + bb1;
            float v2 = acc[mi][ni][2] + bb0;
            float v3 = acc[mi][ni][3] + bb1;
            if (RELU) {
                v0 = fmaxf(v0, 0.f); v1 = fmaxf(v1, 0.f);
                v2 = fmaxf(v2, 0.f); v3 = fmaxf(v3, 0.f);
            }
            if (sizeof(OutT) == 2) {
                __half2* p0 = (__half2*)((__half*)C + (size_t)row0 * N + col);
                __half2* p1 = (__half2*)((__half*)C + (size_t)(row0 + 8) * N + col);
                *p0 = __floats2half2_rn(v0, v1);
                *p1 = __floats2half2_rn(v2, v3);
            } else {
                *(float2*)((float*)C + (size_t)row0 * N + col)       = make_float2(v0, v1);
                *(float2*)((float*)C + (size_t)(row0 + 8) * N + col) = make_float2(v2, v3);
            }
        }
    }
}

// ---------------------------------------------------------------------------
// Head: shared = h2 @ W3^T + b3 (N=4), then per-scene routed 2x2 transforms.
// h2 is fp16 (8.4MB read). One warp per output row.
// ---------------------------------------------------------------------------
__global__ void head_kernel(const __half* __restrict__ h2,
                            const float* __restrict__ W3,
                            const float* __restrict__ b3,
                            const void* __restrict__ sidx,
                            const float* __restrict__ xyW,
                            const float* __restrict__ xyb,
                            const float* __restrict__ tW,
                            float* __restrict__ out)
{
    const int warp = threadIdx.x >> 5;
    const int lane = threadIdx.x & 31;
    const int row  = blockIdx.x * (blockDim.x >> 5) + warp;

    const uint4* hp = (const uint4*)(h2 + (size_t)row * HID);
    float acc[4] = {0.f, 0.f, 0.f, 0.f};
    #pragma unroll
    for (int j = 0; j < 2; j++) {
        int idx = lane + 32 * j;          // 8-half chunk index (0..63)
        uint4 hv = hp[idx];
        float2 f0 = __half22float2(*(__half2*)&hv.x);
        float2 f1 = __half22float2(*(__half2*)&hv.y);
        float2 f2 = __half22float2(*(__half2*)&hv.z);
        float2 f3 = __half22float2(*(__half2*)&hv.w);
        #pragma unroll
        for (int r = 0; r < 4; r++) {
            const float4* wr = (const float4*)(W3 + r * HID);
            float4 w0 = wr[2 * idx];
            float4 w1 = wr[2 * idx + 1];
            acc[r] += f0.x * w0.x + f0.y * w0.y + f1.x * w0.z + f1.y * w0.w
                    + f2.x * w1.x + f2.y * w1.y + f3.x * w1.z + f3.y * w1.w;
        }
    }
    #pragma unroll
    for (int r = 0; r < 4; r++)
        #pragma unroll
        for (int off = 16; off > 0; off >>= 1)
            acc[r] += __shfl_xor_sync(0xffffffffu, acc[r], off);

    if (lane == 0) {
        float s0 = acc[0] + b3[0];
        float s1 = acc[1] + b3[1];
        float s2 = acc[2] + b3[2];
        float s3 = acc[3] + b3[3];

        int s;
        if (g_idx64) s = (int)((const long long*)sidx)[row];
        else         s = ((const int*)sidx)[row];

        const float* wxy = xyW + s * 4;
        const float* wt  = tW  + s * 4;
        float o0 = wxy[0] * s0 + wxy[1] * s1 + xyb[s * 2 + 0];
        float o1 = wxy[2] * s0 + wxy[3] * s1 + xyb[s * 2 + 1];
        float o2 = wt[0] * s2 + wt[1] * s3;
        float o3 = wt[2] * s2 + wt[3] * s3;
        *(float4*)(out + (size_t)row * 4) = make_float4(o0, o1, o2, o3);
    }
}

// ---------------------------------------------------------------------------
// launch
// ---------------------------------------------------------------------------
extern "C" void kernel_launch(void* const* d_in, const int* in_sizes, int n_in,
                              void* d_out, int out_size)
{
    const float* feat = (const float*)d_in[0];
    const void*  sidx = d_in[1];
    const float* W1   = (const float*)d_in[2];
    const float* b1   = (const float*)d_in[3];
    const float* W2   = (const float*)d_in[4];
    const float* b2   = (const float*)d_in[5];
    const float* W3   = (const float*)d_in[6];
    const float* b3   = (const float*)d_in[7];
    const float* xyW  = (const float*)d_in[8];
    const float* xyb  = (const float*)d_in[9];
    const float* tW   = (const float*)d_in[10];
    float* out = (float*)d_out;

    __half *w1h, *w2h, *h1, *h2;
    cudaGetSymbolAddress((void**)&w1h, g_w1h);
    cudaGetSymbolAddress((void**)&w2h, g_w2h);
    cudaGetSymbolAddress((void**)&h1, g_h1);
    cudaGetSymbolAddress((void**)&h2, g_h2);

    constexpr int BM = 128, BN = 256, BK = 64, STG = 3;
    // GEMM1 (fp32 A): 3 * (128*68*4 + 256*72*2) = 215,040 B
    constexpr int SMEM1 = STG * (BM * (BK + 4) * 4 + BN * (BK + 8) * 2);
    // GEMM2 (fp16 A): 3 * (128*72 + 256*72) * 2 = 165,888 B
    constexpr int SMEM2 = STG * (BM * (BK + 8) + BN * (BK + 8)) * 2;

    cudaFuncSetAttribute(gemm_relu_f16<BM, BN, BK, STG, true, true, __half>,
                         cudaFuncAttributeMaxDynamicSharedMemorySize, SMEM1);
    cudaFuncSetAttribute(gemm_relu_f16<BM, BN, BK, STG, true, false, __half>,
                         cudaFuncAttributeMaxDynamicSharedMemorySize, SMEM2);

    detect_idx_kernel<<<1, 1>>>((const int*)sidx);

    // Convert only the weights (8.4 MB, ~3us). feat stays fp32; GEMM1
    // converts it in the fragment path.
    convert_w_kernel<<<512, 256>>>((const float4*)W1, (uint2*)w1h,
                                   (const float4*)W2, (uint2*)w2h);

    dim3 grid(HID / BN, B_ROWS / BM);   // (2, 64) = 128 CTAs
    // GEMM1: relu(feat_fp32 @ W1^T + b1) -> h1 (fp16)
    gemm_relu_f16<BM, BN, BK, STG, true, true, __half><<<grid, 256, SMEM1>>>(
        feat, w1h, b1, h1, B_ROWS, HID, FEAT);
    // GEMM2: relu(h1 @ W2^T + b2) -> h2 (fp16)
    gemm_relu_f16<BM, BN, BK, STG, true, false, __half><<<grid, 256, SMEM2>>>(
        h1, w2h, b2, h2, B_ROWS, HID, HID);
    // Head
    head_kernel<<<B_ROWS / 8, 256>>>(h2, W3, b3, sidx, xyW, xyb, tW, out);
}

// round 15
// speedup vs baseline: 1.5953x; 1.5953x over previous
#include <cuda_runtime.h>
#include <cuda_fp16.h>
#include <cstdint>
#include <cstddef>

// Problem constants
#define B_ROWS 8192
#define FEAT   7680
#define HID    512

// Scratch (allocation-free: __device__ globals)
__device__ __half g_w1h[(size_t)HID * FEAT];         // 7.9 MB
__device__ __half g_w2h[(size_t)HID * HID];          // 0.5 MB
__device__ __half g_h1[(size_t)B_ROWS * HID];        // 8.4 MB (fp16 activations)
__device__ __half g_h2[(size_t)B_ROWS * HID];        // 8.4 MB (fp16 activations)
__device__ int    g_idx64;

// ---------------------------------------------------------------------------
// helpers
// ---------------------------------------------------------------------------
__device__ __forceinline__ void cp_async16(uint32_t smem_dst, const void* gptr) {
    asm volatile("cp.async.cg.shared.global [%0], [%1], 16;"
                 :: "r"(smem_dst), "l"(gptr));
}
__device__ __forceinline__ void cp_commit() {
    asm volatile("cp.async.commit_group;");
}
__device__ __forceinline__ uint32_t packf2(float x, float y) {
    __half2 h = __floats2half2_rn(x, y);
    return *(uint32_t*)&h;
}

// ---------------------------------------------------------------------------
// fp32 -> fp16 conversion for the two weight matrices (8.4MB, ~3us).
// ---------------------------------------------------------------------------
__device__ __forceinline__ void cvt_range(const float4* __restrict__ in,
                                          uint2* __restrict__ out, int n4,
                                          int gtid, int stride)
{
    for (int i = gtid; i < n4; i += stride) {
        float4 v = in[i];
        uint2 u;
        u.x = packf2(v.x, v.y);
        u.y = packf2(v.z, v.w);
        out[i] = u;
    }
}

__global__ void convert_w_kernel(const float4* __restrict__ w1, uint2* __restrict__ w1_o,
                                 const float4* __restrict__ w2, uint2* __restrict__ w2_o)
{
    const int gtid   = blockIdx.x * blockDim.x + threadIdx.x;
    const int stride = gridDim.x * blockDim.x;
    cvt_range(w1, w1_o, (HID * FEAT) / 4, gtid, stride);
    cvt_range(w2, w2_o, (HID * HID) / 4,  gtid, stride);
}

// ---------------------------------------------------------------------------
// scene_idx dtype detection (int32 vs int64).
// ---------------------------------------------------------------------------
__global__ void detect_idx_kernel(const int* __restrict__ p) {
    int is64 = 1;
    for (int i = 0; i < 64; i++) {
        if (p[2 * i + 1] != 0) { is64 = 0; break; }
    }
    g_idx64 = is64;
}

// ===========================================================================
// GEMM1: h1[M,HID] = relu( feat_fp32[M,K] @ W1h[HID,K]^T + b1 ), output fp16.
// CTA 128x256x64, 8 warps 2(M)x4(N), warp tile 64x64 m16n8k16 -- the exact
// R10 MMA loop (measured at the legacy-HMMA roofline). The ONLY addition is
// a convert phase: fp32 A is staged by cp.async (STG=2), then all 256
// threads rewrite the tile into a single fp16 buffer (R10 layout) between
// two barriers. Fragment path is byte-identical to R10.
// smem: 2*34816 (A32) + 2*36864 (B) + 18432 (A16) = 161,792 B.
// ===========================================================================
__global__ void __launch_bounds__(256, 1) gemm1_f32a(
    const float* __restrict__ A, const __half* __restrict__ Bw,
    const float* __restrict__ bias, __half* __restrict__ C)
{
    constexpr int BM = 128, BN = 256, BK = 64;
    constexpr int KT = FEAT / BK;               // 120
    constexpr int SKA32 = BK + 4;               // 68 floats  (272 B row)
    constexpr int SKA16 = BK + 8;               // 72 halves  (144 B row)
    constexpr int SKB   = BK + 8;               // 72 halves
    constexpr int A32_BYTES = BM * SKA32 * 4;   // 34,816
    constexpr int B_BYTES   = BN * SKB * 2;     // 36,864
    constexpr int OFF_B     = 2 * A32_BYTES;
    constexpr int OFF_A16   = OFF_B + 2 * B_BYTES;

    extern __shared__ char smem[];

    const int tid  = threadIdx.x;
    const int warp = tid >> 5;
    const int lane = tid & 31;
    const int g    = lane >> 2;
    const int t4   = lane & 3;

    const int m0 = blockIdx.y * BM;
    const int n0 = blockIdx.x * BN;
    const int wm = (warp & 1) * 64;
    const int wn = (warp >> 1) * 64;

    float acc[4][8][4];
    #pragma unroll
    for (int i = 0; i < 4; i++)
        #pragma unroll
        for (int j = 0; j < 8; j++)
            #pragma unroll
            for (int k = 0; k < 4; k++) acc[i][j][k] = 0.f;

    auto load_stage = [&](int s, int k0) {
        float* As = (float*)(smem + s * A32_BYTES);
        // A fp32: 128 rows x 16 chunks(16B) = 2048 / 256 thr = 8 each
        #pragma unroll
        for (int i = 0; i < 8; i++) {
            int q = tid + i * 256;
            int row = q >> 4, c = q & 15;
            cp_async16((uint32_t)__cvta_generic_to_shared(As + row * SKA32 + c * 4),
                       A + (size_t)(m0 + row) * FEAT + k0 + c * 4);
        }
        __half* Bs = (__half*)(smem + OFF_B + s * B_BYTES);
        // B fp16: 256 rows x 8 chunks = 2048 / 256 thr = 8 each
        #pragma unroll
        for (int i = 0; i < 8; i++) {
            int q = tid + i * 256;
            int row = q >> 3, c = q & 7;
            cp_async16((uint32_t)__cvta_generic_to_shared(Bs + row * SKB + c * 8),
                       Bw + (size_t)(n0 + row) * FEAT + k0 + c * 8);
        }
    };

    load_stage(0, 0);
    cp_commit();

    for (int kt = 0; kt < KT; kt++) {
        const int slot = kt & 1;

        asm volatile("cp.async.wait_group 0;");
        __syncthreads();   // stage `slot` ready; prior MMA/convert readers done

        int kn = kt + 1;
        if (kn < KT) load_stage(kn & 1, kn * BK);
        cp_commit();       // empty group at tail keeps accounting trivial

        // ---- convert phase: fp32 slot -> fp16 buffer (R10 layout) ----
        {
            const float* As32 = (const float*)(smem + slot * A32_BYTES);
            __half* A16 = (__half*)(smem + OFF_A16);
            const int row = tid >> 1;
            const int cb  = (tid & 1) * 32;
            const float* src = As32 + row * SKA32 + cb;
            __half* dst = A16 + row * SKA16 + cb;
            #pragma unroll
            for (int c = 0; c < 8; c++) {
                float4 v = *(const float4*)(src + c * 4);
                uint2 u;
                u.x = packf2(v.x, v.y);
                u.y = packf2(v.z, v.w);
                *(uint2*)(dst + c * 4) = u;
            }
        }
        __syncthreads();   // convert writes visible to all warps

        // ---- MMA section: byte-identical to R10 ----
        const __half* As = (const __half*)(smem + OFF_A16);
        const __half* Bs = (const __half*)(smem + OFF_B + slot * B_BYTES);

        #pragma unroll
        for (int kk = 0; kk < BK / 16; kk++) {
            uint32_t b[8][2];
            #pragma unroll
            for (int ni = 0; ni < 8; ni++) {
                const __half* bp = Bs + (wn + ni * 8 + g) * SKB + kk * 16 + t4 * 2;
                b[ni][0] = *(const uint32_t*)bp;
                b[ni][1] = *(const uint32_t*)(bp + 8);
            }
            #pragma unroll
            for (int mi = 0; mi < 4; mi++) {
                const __half* ap  = As + (wm + mi * 16 + g) * SKA16 + kk * 16 + t4 * 2;
                const __half* ap8 = ap + 8 * SKA16;
                uint32_t a0 = *(const uint32_t*)ap;
                uint32_t a1 = *(const uint32_t*)ap8;
                uint32_t a2 = *(const uint32_t*)(ap + 8);
                uint32_t a3 = *(const uint32_t*)(ap8 + 8);
                #pragma unroll
                for (int ni = 0; ni < 8; ni++) {
                    float* d = acc[mi][ni];
                    asm volatile(
                        "mma.sync.aligned.m16n8k16.row.col.f32.f16.f16.f32 "
                        "{%0,%1,%2,%3}, {%4,%5,%6,%7}, {%8,%9}, {%0,%1,%2,%3};"
                        : "+f"(d[0]), "+f"(d[1]), "+f"(d[2]), "+f"(d[3])
                        : "r"(a0), "r"(a1), "r"(a2), "r"(a3),
                          "r"(b[ni][0]), "r"(b[ni][1]));
                }
            }
        }
    }

    // Epilogue: bias + ReLU -> fp16
    #pragma unroll
    for (int mi = 0; mi < 4; mi++) {
        int row0 = m0 + wm + mi * 16 + g;
        #pragma unroll
        for (int ni = 0; ni < 8; ni++) {
            int col = n0 + wn + ni * 8 + t4 * 2;
            float bb0 = bias[col], bb1 = bias[col + 1];
            float v0 = fmaxf(acc[mi][ni][0] + bb0, 0.f);
            float v1 = fmaxf(acc[mi][ni][1] + bb1, 0.f);
            float v2 = fmaxf(acc[mi][ni][2] + bb0, 0.f);
            float v3 = fmaxf(acc[mi][ni][3] + bb1, 0.f);
            *(uint32_t*)(C + (size_t)row0 * HID + col)       = packf2(v0, v1);
            *(uint32_t*)(C + (size_t)(row0 + 8) * HID + col) = packf2(v2, v3);
        }
    }
}

// ===========================================================================
// GEMM2: h2[M,HID] = relu( h1_fp16[M,K] @ W2h[HID,K]^T + b2 ), output fp16.
// Exact R10 kernel (fp16 cp.async producers, STG=4).
// ===========================================================================
__global__ void __launch_bounds__(256, 1) gemm2_f16(
    const __half* __restrict__ A, const __half* __restrict__ Bw,
    const float* __restrict__ bias, __half* __restrict__ C)
{
    constexpr int BM = 128, BN = 256, BK = 64, STAGES = 4;
    constexpr int K = HID, N = HID;
    constexpr int KT = K / BK;                  // 8
    constexpr int SKA = BK + 8;
    constexpr int SKB = BK + 8;
    constexpr int STAGE_H = BM * SKA + BN * SKB;

    extern __shared__ __half smemh[];

    const int tid  = threadIdx.x;
    const int warp = tid >> 5;
    const int lane = tid & 31;
    const int g    = lane >> 2;
    const int t4   = lane & 3;

    const int m0 = blockIdx.y * BM;
    const int n0 = blockIdx.x * BN;
    const int wm = (warp & 1) * 64;
    const int wn = (warp >> 1) * 64;

    float acc[4][8][4];
    #pragma unroll
    for (int i = 0; i < 4; i++)
        #pragma unroll
        for (int j = 0; j < 8; j++)
            #pragma unroll
            for (int k = 0; k < 4; k++) acc[i][j][k] = 0.f;

    auto load_stage = [&](int s, int k0) {
        __half* As = smemh + s * STAGE_H;
        __half* Bs = As + BM * SKA;
        #pragma unroll
        for (int i = 0; i < 4; i++) {
            int q = tid + i * 256;
            int row = q >> 3, c = q & 7;
            cp_async16((uint32_t)__cvta_generic_to_shared(As + row * SKA + c * 8),
                       A + (size_t)(m0 + row) * K + k0 + c * 8);
        }
        #pragma unroll
        for (int i = 0; i < 8; i++) {
            int q = tid + i * 256;
            int row = q >> 3, c = q & 7;
            cp_async16((uint32_t)__cvta_generic_to_shared(Bs + row * SKB + c * 8),
                       Bw + (size_t)(n0 + row) * K + k0 + c * 8);
        }
    };

    #pragma unroll
    for (int s = 0; s < STAGES - 1; s++) {
        load_stage(s, s * BK);
        cp_commit();
    }

    int buf = 0;
    for (int kt = 0; kt < KT; kt++) {
        asm volatile("cp.async.wait_group %0;" :: "n"(STAGES - 2));
        __syncthreads();

        int kn = kt + STAGES - 1;
        if (kn < KT) load_stage(kn % STAGES, kn * BK);
        cp_commit();

        const __half* As = smemh + buf * STAGE_H;
        const __half* Bs = As + BM * SKA;

        #pragma unroll
        for (int kk = 0; kk < BK / 16; kk++) {
            uint32_t b[8][2];
            #pragma unroll
            for (int ni = 0; ni < 8; ni++) {
                const __half* bp = Bs + (wn + ni * 8 + g) * SKB + kk * 16 + t4 * 2;
                b[ni][0] = *(const uint32_t*)bp;
                b[ni][1] = *(const uint32_t*)(bp + 8);
            }
            #pragma unroll
            for (int mi = 0; mi < 4; mi++) {
                const __half* ap  = As + (wm + mi * 16 + g) * SKA + kk * 16 + t4 * 2;
                const __half* ap8 = ap + 8 * SKA;
                uint32_t a0 = *(const uint32_t*)ap;
                uint32_t a1 = *(const uint32_t*)ap8;
                uint32_t a2 = *(const uint32_t*)(ap + 8);
                uint32_t a3 = *(const uint32_t*)(ap8 + 8);
                #pragma unroll
                for (int ni = 0; ni < 8; ni++) {
                    float* d = acc[mi][ni];
                    asm volatile(
                        "mma.sync.aligned.m16n8k16.row.col.f32.f16.f16.f32 "
                        "{%0,%1,%2,%3}, {%4,%5,%6,%7}, {%8,%9}, {%0,%1,%2,%3};"
                        : "+f"(d[0]), "+f"(d[1]), "+f"(d[2]), "+f"(d[3])
                        : "r"(a0), "r"(a1), "r"(a2), "r"(a3),
                          "r"(b[ni][0]), "r"(b[ni][1]));
                }
            }
        }

        buf++;
        if (buf == STAGES) buf = 0;
    }

    #pragma unroll
    for (int mi = 0; mi < 4; mi++) {
        int row0 = m0 + wm + mi * 16 + g;
        #pragma unroll
        for (int ni = 0; ni < 8; ni++) {
            int col = n0 + wn + ni * 8 + t4 * 2;
            float bb0 = bias[col], bb1 = bias[col + 1];
            float v0 = fmaxf(acc[mi][ni][0] + bb0, 0.f);
            float v1 = fmaxf(acc[mi][ni][1] + bb1, 0.f);
            float v2 = fmaxf(acc[mi][ni][2] + bb0, 0.f);
            float v3 = fmaxf(acc[mi][ni][3] + bb1, 0.f);
            *(uint32_t*)(C + (size_t)row0 * N + col)       = packf2(v0, v1);
            *(uint32_t*)(C + (size_t)(row0 + 8) * N + col) = packf2(v2, v3);
        }
    }
}

// ---------------------------------------------------------------------------
// Head: shared = h2 @ W3^T + b3 (N=4), then per-scene routed 2x2 transforms.
// h2 is fp16 (8.4MB read). One warp per output row.
// ---------------------------------------------------------------------------
__global__ void head_kernel(const __half* __restrict__ h2,
                            const float* __restrict__ W3,
                            const float* __restrict__ b3,
                            const void* __restrict__ sidx,
                            const float* __restrict__ xyW,
                            const float* __restrict__ xyb,
                            const float* __restrict__ tW,
                            float* __restrict__ out)
{
    const int warp = threadIdx.x >> 5;
    const int lane = threadIdx.x & 31;
    const int row  = blockIdx.x * (blockDim.x >> 5) + warp;

    const uint4* hp = (const uint4*)(h2 + (size_t)row * HID);
    float acc[4] = {0.f, 0.f, 0.f, 0.f};
    #pragma unroll
    for (int j = 0; j < 2; j++) {
        int idx = lane + 32 * j;          // 8-half chunk index (0..63)
        uint4 hv = hp[idx];
        float2 f0 = __half22float2(*(__half2*)&hv.x);
        float2 f1 = __half22float2(*(__half2*)&hv.y);
        float2 f2 = __half22float2(*(__half2*)&hv.z);
        float2 f3 = __half22float2(*(__half2*)&hv.w);
        #pragma unroll
        for (int r = 0; r < 4; r++) {
            const float4* wr = (const float4*)(W3 + r * HID);
            float4 w0 = wr[2 * idx];
            float4 w1 = wr[2 * idx + 1];
            acc[r] += f0.x * w0.x + f0.y * w0.y + f1.x * w0.z + f1.y * w0.w
                    + f2.x * w1.x + f2.y * w1.y + f3.x * w1.z + f3.y * w1.w;
        }
    }
    #pragma unroll
    for (int r = 0; r < 4; r++)
        #pragma unroll
        for (int off = 16; off > 0; off >>= 1)
            acc[r] += __shfl_xor_sync(0xffffffffu, acc[r], off);

    if (lane == 0) {
        float s0 = acc[0] + b3[0];
        float s1 = acc[1] + b3[1];
        float s2 = acc[2] + b3[2];
        float s3 = acc[3] + b3[3];

        int s;
        if (g_idx64) s = (int)((const long long*)sidx)[row];
        else         s = ((const int*)sidx)[row];

        const float* wxy = xyW + s * 4;
        const float* wt  = tW  + s * 4;
        float o0 = wxy[0] * s0 + wxy[1] * s1 + xyb[s * 2 + 0];
        float o1 = wxy[2] * s0 + wxy[3] * s1 + xyb[s * 2 + 1];
        float o2 = wt[0] * s2 + wt[1] * s3;
        float o3 = wt[2] * s2 + wt[3] * s3;
        *(float4*)(out + (size_t)row * 4) = make_float4(o0, o1, o2, o3);
    }
}

// ---------------------------------------------------------------------------
// launch
// ---------------------------------------------------------------------------
extern "C" void kernel_launch(void* const* d_in, const int* in_sizes, int n_in,
                              void* d_out, int out_size)
{
    const float* feat = (const float*)d_in[0];
    const void*  sidx = d_in[1];
    const float* W1   = (const float*)d_in[2];
    const float* b1   = (const float*)d_in[3];
    const float* W2   = (const float*)d_in[4];
    const float* b2   = (const float*)d_in[5];
    const float* W3   = (const float*)d_in[6];
    const float* b3   = (const float*)d_in[7];
    const float* xyW  = (const float*)d_in[8];
    const float* xyb  = (const float*)d_in[9];
    const float* tW   = (const float*)d_in[10];
    float* out = (float*)d_out;

    __half *w1h, *w2h, *h1, *h2;
    cudaGetSymbolAddress((void**)&w1h, g_w1h);
    cudaGetSymbolAddress((void**)&w2h, g_w2h);
    cudaGetSymbolAddress((void**)&h1, g_h1);
    cudaGetSymbolAddress((void**)&h2, g_h2);

    // GEMM1 smem: 2*34816 + 2*36864 + 18432 = 161,792 B
    constexpr int SMEM1 = 2 * (128 * 68 * 4) + 2 * (256 * 72 * 2) + 128 * 72 * 2;
    // GEMM2 smem: 4 * (128*72 + 256*72) * 2 = 221,184 B
    constexpr int SMEM2 = 4 * (128 * 72 + 256 * 72) * 2;

    cudaFuncSetAttribute(gemm1_f32a,
                         cudaFuncAttributeMaxDynamicSharedMemorySize, SMEM1);
    cudaFuncSetAttribute(gemm2_f16,
                         cudaFuncAttributeMaxDynamicSharedMemorySize, SMEM2);

    detect_idx_kernel<<<1, 1>>>((const int*)sidx);

    // Convert only the weights (8.4 MB, ~3us). feat stays fp32; GEMM1
    // converts tiles in a dedicated smem phase.
    convert_w_kernel<<<512, 256>>>((const float4*)W1, (uint2*)w1h,
                                   (const float4*)W2, (uint2*)w2h);

    dim3 grid(HID / 256, B_ROWS / 128);   // (2, 64) = 128 CTAs
    gemm1_f32a<<<grid, 256, SMEM1>>>(feat, w1h, b1, h1);
    gemm2_f16<<<grid, 256, SMEM2>>>(h1, w2h, b2, h2);
    head_kernel<<<B_ROWS / 8, 256>>>(h2, W3, b3, sidx, xyW, xyb, tW, out);
}